// round 14
// baseline (speedup 1.0000x reference)
#include <cuda_runtime.h>
#include <cuda_fp16.h>
#include <cstdint>
#include <cstddef>

#define TOKENS 32768
#define HIDDEN 2048
#define INTER  1408
#define NEXP   16
#define TPE    2048

#define BM 128
#define BK 32
#define PAD 40
#define NSTAGE 4
#define SMEM_BYTES (NSTAGE * (128 * PAD + 128 * PAD) * 2)

#define NT1 ((TOKENS / BM) * (INTER / 64))    // 5632 gemm1 tiles
#define NT2 ((TOKENS / BM) * (HIDDEN / 128))  // 4096 gemm2 tiles

// ---------------- static device scratch ----------------
__device__ __align__(128) __half g_Xh[(size_t)TOKENS * HIDDEN];
__device__ __align__(128) __half g_Wg[(size_t)NEXP * INTER * HIDDEN];   // [e][n][k]
__device__ __align__(128) __half g_Wu[(size_t)NEXP * INTER * HIDDEN];   // [e][n][k]
__device__ __align__(128) __half g_Wd[(size_t)NEXP * HIDDEN * INTER];   // [e][n][k]
__device__ __align__(128) __half g_H [(size_t)TOKENS * INTER];

// ---------------- helpers ----------------
__device__ __forceinline__ uint32_t smem_u32(const void* p) {
    return (uint32_t)__cvta_generic_to_shared(p);
}
__device__ __forceinline__ void cp_async16(uint32_t dst, const void* src) {
    asm volatile("cp.async.cg.shared.global [%0], [%1], 16;\n" :: "r"(dst), "l"(src));
}
__device__ __forceinline__ void cp_commit() {
    asm volatile("cp.async.commit_group;\n" ::: "memory");
}
template <int N>
__device__ __forceinline__ void cp_wait() {
    asm volatile("cp.async.wait_group %0;\n" :: "n"(N) : "memory");
}
__device__ __forceinline__ void ldsm_x4(uint32_t addr, uint32_t& r0, uint32_t& r1,
                                        uint32_t& r2, uint32_t& r3) {
    asm volatile("ldmatrix.sync.aligned.m8n8.x4.shared.b16 {%0,%1,%2,%3}, [%4];\n"
                 : "=r"(r0), "=r"(r1), "=r"(r2), "=r"(r3) : "r"(addr));
}
__device__ __forceinline__ void mma16816(float* c, const uint32_t* a, const uint32_t* b) {
    asm volatile(
        "mma.sync.aligned.m16n8k16.row.col.f32.f16.f16.f32 "
        "{%0,%1,%2,%3}, {%4,%5,%6,%7}, {%8,%9}, {%0,%1,%2,%3};\n"
        : "+f"(c[0]), "+f"(c[1]), "+f"(c[2]), "+f"(c[3])
        : "r"(a[0]), "r"(a[1]), "r"(a[2]), "r"(a[3]), "r"(b[0]), "r"(b[1]));
}

// ---------------- 1. X fp32 -> fp16 ----------------
__global__ void convert_x_kernel(const float* __restrict__ x, size_t n8) {
    size_t i = (size_t)blockIdx.x * blockDim.x + threadIdx.x;
    if (i >= n8) return;
    const float4* x4 = (const float4*)x;
    float4 a = x4[2 * i];
    float4 b = x4[2 * i + 1];
    union { __half2 h[4]; uint4 u; } r;
    r.h[0] = __floats2half2_rn(a.x, a.y);
    r.h[1] = __floats2half2_rn(a.z, a.w);
    r.h[2] = __floats2half2_rn(b.x, b.y);
    r.h[3] = __floats2half2_rn(b.z, b.w);
    ((uint4*)g_Xh)[i] = r.u;
}

// ---------------- 2a. gate+up transpose+convert (merged, swizzled smem) ----------------
__global__ __launch_bounds__(256) void wconv_gu_kernel(const float* __restrict__ wg,
                                                       const float* __restrict__ wu) {
    __shared__ __half s[64][66];
    const int sel = blockIdx.z >> 4;
    const int e = blockIdx.z & 15;
    const float* src = sel ? wu : wg;
    __half* dst = sel ? g_Wu : g_Wg;
    const int K = HIDDEN, N = INTER;
    int n0 = blockIdx.x * 64, k0 = blockIdx.y * 64;
    const float* sp = src + (size_t)e * K * N + (size_t)k0 * N + n0;
    int tid = threadIdx.x;
    int nc = (tid & 15) * 4;
    #pragma unroll
    for (int p = 0; p < 4; p++) {
        int kr = (tid >> 4) + p * 16;
        int col = nc ^ (p * 16);
        float4 v = *(const float4*)(sp + (size_t)kr * N + nc);
        s[kr][col + 0] = __float2half_rn(v.x);
        s[kr][col + 1] = __float2half_rn(v.y);
        s[kr][col + 2] = __float2half_rn(v.z);
        s[kr][col + 3] = __float2half_rn(v.w);
    }
    __syncthreads();
    __half* dp = dst + (size_t)e * N * K + (size_t)n0 * K + k0;
    int nr = tid >> 2;
    int c = tid & 3;
    int colr = nr ^ (c * 16);
    union { uint2 u2[4]; uint4 u4[2]; } v;
    #pragma unroll
    for (int q = 0; q < 4; q++) {
        int kk = c * 16 + q * 4;
        __half2 lo = __halves2half2(s[kk + 0][colr], s[kk + 1][colr]);
        __half2 hi = __halves2half2(s[kk + 2][colr], s[kk + 3][colr]);
        v.u2[q] = make_uint2(*(uint32_t*)&lo, *(uint32_t*)&hi);
    }
    *(uint4*)(dp + (size_t)nr * K + c * 16) = v.u4[0];
    *(uint4*)(dp + (size_t)nr * K + c * 16 + 8) = v.u4[1];
}

// ---------------- 2b. down-proj transpose+convert (side stream, overlaps gemm1) --------
__global__ __launch_bounds__(128) void wconv_d_kernel(const float* __restrict__ wd) {
    __shared__ __half s[64][66];
    const int e = blockIdx.z;
    const int K = INTER, N = HIDDEN;
    int n0 = blockIdx.x * 64, k0 = blockIdx.y * 64;
    const float* sp = wd + (size_t)e * K * N + (size_t)k0 * N + n0;
    int tid = threadIdx.x;
    int nc = (tid & 15) * 4;
    #pragma unroll
    for (int p = 0; p < 8; p++) {
        int kr = (tid >> 4) + p * 8;
        int col = nc ^ ((p >> 1) * 16);
        float4 v = *(const float4*)(sp + (size_t)kr * N + nc);
        s[kr][col + 0] = __float2half_rn(v.x);
        s[kr][col + 1] = __float2half_rn(v.y);
        s[kr][col + 2] = __float2half_rn(v.z);
        s[kr][col + 3] = __float2half_rn(v.w);
    }
    __syncthreads();
    __half* dp = g_Wd + (size_t)e * N * K + (size_t)n0 * K + k0;
    int nr = tid >> 1;
    #pragma unroll
    for (int it = 0; it < 2; it++) {
        int c = (tid & 1) * 2 + it;
        int colr = nr ^ (c * 16);
        union { uint2 u2[4]; uint4 u4[2]; } v;
        #pragma unroll
        for (int q = 0; q < 4; q++) {
            int kk = c * 16 + q * 4;
            __half2 lo = __halves2half2(s[kk + 0][colr], s[kk + 1][colr]);
            __half2 hi = __halves2half2(s[kk + 2][colr], s[kk + 3][colr]);
            v.u2[q] = make_uint2(*(uint32_t*)&lo, *(uint32_t*)&hi);
        }
        *(uint4*)(dp + (size_t)nr * K + c * 16) = v.u4[0];
        *(uint4*)(dp + (size_t)nr * K + c * 16 + 8) = v.u4[1];
    }
}

// ============================================================================
// Persistent GEMM core: 256-thread CTAs, 2/SM, grid = 2*numSMs, tile loop.
// 8 warps (4m x 2n), warp tile 32m x 64 B-rows. Per-iter __syncthreads makes
// cross-tile smem reuse safe (next tile's prologue writes stages 0-2 only;
// stage 3 rewritten after the next in-loop sync).
// ============================================================================

// ---------------- 3. fused gate+up GEMM + SwiGLU -> g_H (fp16) ----------------
__global__ __launch_bounds__(256, 2) void gemm1_kernel() {
    extern __shared__ __half sm[];
    __half (*sA)[128][PAD] = (__half(*)[128][PAD])sm;
    __half (*sB)[128][PAD] = (__half(*)[128][PAD])(sm + NSTAGE * 128 * PAD);

    const int tid = threadIdx.x;
    const int NK = HIDDEN / BK;               // 64
    const int lr = tid >> 2, lc = (tid & 3) * 8;

    uint32_t aAd0[NSTAGE], aAd1[NSTAGE], bAd0[NSTAGE], bAd1[NSTAGE];
    #pragma unroll
    for (int s = 0; s < NSTAGE; s++) {
        aAd0[s] = smem_u32(&sA[s][lr][lc]);
        aAd1[s] = smem_u32(&sA[s][lr + 64][lc]);
        bAd0[s] = smem_u32(&sB[s][lr][lc]);
        bAd1[s] = smem_u32(&sB[s][lr + 64][lc]);
    }

    const int w = tid >> 5, lane = tid & 31;
    const int wm = (w >> 1) * 32;
    const int wn = (w & 1) * 32;
    const int lrow = lane & 15;
    const int lkb = (lane >> 4) * 8;
    const int gr = lane >> 2, gc = (lane & 3) * 2;

    for (int t = blockIdx.x; t < NT1; t += gridDim.x) {
        const int nB = (t % (INTER / 64)) * 64;      // n fastest -> L2 A-sharing
        const int mTile = t / (INTER / 64);
        const int mBase = mTile * BM;
        const int e = mTile >> 4;

        const __half* gA0 = g_Xh + (size_t)(mBase + lr) * HIDDEN + lc;
        const __half* gA1 = gA0 + (size_t)64 * HIDDEN;
        const __half* gBg = g_Wg + ((size_t)e * INTER + nB + lr) * HIDDEN + lc;
        const __half* gBu = g_Wu + ((size_t)e * INTER + nB + lr) * HIDDEN + lc;

        auto load_stage = [&](int s, int k0) {
            cp_async16(aAd0[s], gA0 + k0);
            cp_async16(aAd1[s], gA1 + k0);
            cp_async16(bAd0[s], gBg + k0);
            cp_async16(bAd1[s], gBu + k0);
        };

        float acc[2 * 8 * 4];
        #pragma unroll
        for (int i = 0; i < 64; i++) acc[i] = 0.f;

        #pragma unroll
        for (int i = 0; i < NSTAGE - 1; i++) { load_stage(i, i * BK); cp_commit(); }

        #pragma unroll 1
        for (int k = 0; k < NK; ++k) {
            cp_wait<NSTAGE - 2>();
            __syncthreads();
            int kn = k + NSTAGE - 1;
            if (kn < NK) load_stage(kn & 3, kn * BK);
            cp_commit();
            const int st = k & 3;
            #pragma unroll
            for (int kk = 0; kk < BK; kk += 16) {
                uint32_t a[2][4];
                uint32_t b[8][2];
                #pragma unroll
                for (int mt = 0; mt < 2; mt++)
                    ldsm_x4(smem_u32(&sA[st][wm + mt * 16 + lrow][kk + lkb]),
                            a[mt][0], a[mt][1], a[mt][2], a[mt][3]);
                #pragma unroll
                for (int bt = 0; bt < 2; bt++) {
                    uint32_t r0, r1, r2, r3;
                    ldsm_x4(smem_u32(&sB[st][wn + bt * 16 + lrow][kk + lkb]),
                            r0, r1, r2, r3);
                    b[bt * 2][0] = r0;     b[bt * 2][1] = r2;
                    b[bt * 2 + 1][0] = r1; b[bt * 2 + 1][1] = r3;
                }
                #pragma unroll
                for (int bt = 0; bt < 2; bt++) {
                    uint32_t r0, r1, r2, r3;
                    ldsm_x4(smem_u32(&sB[st][64 + wn + bt * 16 + lrow][kk + lkb]),
                            r0, r1, r2, r3);
                    b[4 + bt * 2][0] = r0;     b[4 + bt * 2][1] = r2;
                    b[4 + bt * 2 + 1][0] = r1; b[4 + bt * 2 + 1][1] = r3;
                }
                #pragma unroll
                for (int mt = 0; mt < 2; mt++)
                    #pragma unroll
                    for (int nt = 0; nt < 8; nt++)
                        mma16816(&acc[(mt * 8 + nt) * 4], a[mt], b[nt]);
            }
        }

        // epilogue: nt 0..3 gate, nt+4 up; SwiGLU -> g_H fp16
        #pragma unroll
        for (int mt = 0; mt < 2; mt++) {
            #pragma unroll
            for (int nt = 0; nt < 4; nt++) {
                const float* g = &acc[(mt * 8 + nt) * 4];
                const float* u = &acc[(mt * 8 + nt + 4) * 4];
                int n = nB + wn + nt * 8 + gc;
                int token = mBase + wm + mt * 16 + gr;
                float h0 = g[0] * u[0] / (1.f + __expf(-g[0]));
                float h1 = g[1] * u[1] / (1.f + __expf(-g[1]));
                float h2 = g[2] * u[2] / (1.f + __expf(-g[2]));
                float h3 = g[3] * u[3] / (1.f + __expf(-g[3]));
                *(__half2*)&g_H[(size_t)token * INTER + n] = __floats2half2_rn(h0, h1);
                *(__half2*)&g_H[(size_t)(token + 8) * INTER + n] = __floats2half2_rn(h2, h3);
            }
        }
    }
}

// ---------------- 4. down GEMM: out = h @ Wd_e (fp32 out), tile 128x128 --------
__global__ __launch_bounds__(256, 2) void gemm2_kernel(float* __restrict__ out) {
    extern __shared__ __half sm[];
    __half (*sA)[128][PAD] = (__half(*)[128][PAD])sm;
    __half (*sB)[128][PAD] = (__half(*)[128][PAD])(sm + NSTAGE * 128 * PAD);

    const int tid = threadIdx.x;
    const int NK = INTER / BK;                // 44
    const int lr = tid >> 2, lc = (tid & 3) * 8;

    uint32_t aAd0[NSTAGE], aAd1[NSTAGE], bAd0[NSTAGE], bAd1[NSTAGE];
    #pragma unroll
    for (int s = 0; s < NSTAGE; s++) {
        aAd0[s] = smem_u32(&sA[s][lr][lc]);
        aAd1[s] = smem_u32(&sA[s][lr + 64][lc]);
        bAd0[s] = smem_u32(&sB[s][lr][lc]);
        bAd1[s] = smem_u32(&sB[s][lr + 64][lc]);
    }

    const int w = tid >> 5, lane = tid & 31;
    const int wm = (w >> 1) * 32;
    const int wn = (w & 1) * 64;
    const int lrow = lane & 15;
    const int lkb = (lane >> 4) * 8;
    const int gr = lane >> 2, gc = (lane & 3) * 2;

    for (int t = blockIdx.x; t < NT2; t += gridDim.x) {
        const int nB = (t % (HIDDEN / 128)) * 128;
        const int mTile = t / (HIDDEN / 128);
        const int mBase = mTile * BM;
        const int e = mTile >> 4;

        const __half* gA0 = g_H + (size_t)(mBase + lr) * INTER + lc;
        const __half* gA1 = gA0 + (size_t)64 * INTER;
        const __half* gB0 = g_Wd + ((size_t)e * HIDDEN + nB + lr) * INTER + lc;
        const __half* gB1 = gB0 + (size_t)64 * INTER;

        auto load_stage = [&](int s, int k0) {
            cp_async16(aAd0[s], gA0 + k0);
            cp_async16(aAd1[s], gA1 + k0);
            cp_async16(bAd0[s], gB0 + k0);
            cp_async16(bAd1[s], gB1 + k0);
        };

        float acc[2 * 8 * 4];
        #pragma unroll
        for (int i = 0; i < 64; i++) acc[i] = 0.f;

        #pragma unroll
        for (int i = 0; i < NSTAGE - 1; i++) { load_stage(i, i * BK); cp_commit(); }

        #pragma unroll 1
        for (int k = 0; k < NK; ++k) {
            cp_wait<NSTAGE - 2>();
            __syncthreads();
            int kn = k + NSTAGE - 1;
            if (kn < NK) load_stage(kn & 3, kn * BK);
            cp_commit();
            const int st = k & 3;
            #pragma unroll
            for (int kk = 0; kk < BK; kk += 16) {
                uint32_t a[2][4];
                uint32_t b[8][2];
                #pragma unroll
                for (int mt = 0; mt < 2; mt++)
                    ldsm_x4(smem_u32(&sA[st][wm + mt * 16 + lrow][kk + lkb]),
                            a[mt][0], a[mt][1], a[mt][2], a[mt][3]);
                #pragma unroll
                for (int bt = 0; bt < 4; bt++) {
                    uint32_t r0, r1, r2, r3;
                    ldsm_x4(smem_u32(&sB[st][wn + bt * 16 + lrow][kk + lkb]),
                            r0, r1, r2, r3);
                    b[bt * 2][0] = r0;     b[bt * 2][1] = r2;
                    b[bt * 2 + 1][0] = r1; b[bt * 2 + 1][1] = r3;
                }
                #pragma unroll
                for (int mt = 0; mt < 2; mt++)
                    #pragma unroll
                    for (int nt = 0; nt < 8; nt++)
                        mma16816(&acc[(mt * 8 + nt) * 4], a[mt], b[nt]);
            }
        }

        #pragma unroll
        for (int mt = 0; mt < 2; mt++) {
            #pragma unroll
            for (int nt = 0; nt < 8; nt++) {
                const float* c = &acc[(mt * 8 + nt) * 4];
                int n = nB + wn + nt * 8 + gc;
                int token = mBase + wm + mt * 16 + gr;
                *(float2*)&out[(size_t)token * HIDDEN + n] = make_float2(c[0], c[1]);
                *(float2*)&out[(size_t)(token + 8) * HIDDEN + n] = make_float2(c[2], c[3]);
            }
        }
    }
}

// ---------------- launch ----------------
extern "C" void kernel_launch(void* const* d_in, const int* in_sizes, int n_in,
                              void* d_out, int out_size) {
    const float* x  = (const float*)d_in[0];
    const float* wg = (const float*)d_in[1];
    const float* wu = (const float*)d_in[2];
    const float* wd = (const float*)d_in[3];
    (void)in_sizes; (void)n_in; (void)out_size;

    static cudaStream_t s2 = nullptr;
    static cudaEvent_t evFork = nullptr, evJoin = nullptr;
    static int nPersist = 0;
    if (!s2) {
        cudaStreamCreateWithFlags(&s2, cudaStreamNonBlocking);
        cudaEventCreateWithFlags(&evFork, cudaEventDisableTiming);
        cudaEventCreateWithFlags(&evJoin, cudaEventDisableTiming);
        cudaFuncSetAttribute(gemm1_kernel, cudaFuncAttributeMaxDynamicSharedMemorySize,
                             SMEM_BYTES);
        cudaFuncSetAttribute(gemm2_kernel, cudaFuncAttributeMaxDynamicSharedMemorySize,
                             SMEM_BYTES);
        int dev = 0, sms = 148;
        cudaGetDevice(&dev);
        cudaDeviceGetAttribute(&sms, cudaDevAttrMultiProcessorCount, dev);
        nPersist = 2 * sms;
    }

    // converts first (full DRAM BW)
    size_t n8 = (size_t)TOKENS * HIDDEN / 8;
    convert_x_kernel<<<(unsigned)((n8 + 255) / 256), 256>>>(x, n8);
    wconv_gu_kernel<<<dim3(INTER / 64, HIDDEN / 64, 2 * NEXP), 256>>>(wg, wu);

    // fork: wconv_d overlaps gemm1 (compute-bound, spare DRAM BW)
    cudaEventRecord(evFork, 0);
    cudaStreamWaitEvent(s2, evFork, 0);
    wconv_d_kernel<<<dim3(HIDDEN / 64, INTER / 64, NEXP), 128, 0, s2>>>(wd);
    cudaEventRecord(evJoin, s2);

    // persistent GEMMs: no wave-quantization tail
    gemm1_kernel<<<nPersist, 256, SMEM_BYTES>>>();

    cudaStreamWaitEvent(0, evJoin, 0);
    gemm2_kernel<<<nPersist, 256, SMEM_BYTES>>>((float*)d_out);
}

// round 15
// speedup vs baseline: 1.0786x; 1.0786x over previous
#include <cuda_runtime.h>
#include <cuda_fp16.h>
#include <cstdint>
#include <cstddef>

#define TOKENS 32768
#define HIDDEN 2048
#define INTER  1408
#define NEXP   16
#define TPE    2048

#define BM 128
#define BK 32
#define PAD 40
#define NSTAGE 4
#define SMEM_BYTES (NSTAGE * (128 * PAD + 128 * PAD) * 2)

// ---------------- static device scratch ----------------
__device__ __align__(128) __half g_Xh[(size_t)TOKENS * HIDDEN];
__device__ __align__(128) __half g_Wg[(size_t)NEXP * INTER * HIDDEN];   // [e][n][k]
__device__ __align__(128) __half g_Wu[(size_t)NEXP * INTER * HIDDEN];   // [e][n][k]
__device__ __align__(128) __half g_Wd[(size_t)NEXP * HIDDEN * INTER];   // [e][n][k]
__device__ __align__(128) __half g_H [(size_t)TOKENS * INTER];

// ---------------- helpers ----------------
__device__ __forceinline__ uint32_t smem_u32(const void* p) {
    return (uint32_t)__cvta_generic_to_shared(p);
}
__device__ __forceinline__ void cp_async16(uint32_t dst, const void* src) {
    asm volatile("cp.async.cg.shared.global [%0], [%1], 16;\n" :: "r"(dst), "l"(src));
}
__device__ __forceinline__ void cp_commit() {
    asm volatile("cp.async.commit_group;\n" ::: "memory");
}
template <int N>
__device__ __forceinline__ void cp_wait() {
    asm volatile("cp.async.wait_group %0;\n" :: "n"(N) : "memory");
}
__device__ __forceinline__ void ldsm_x4(uint32_t addr, uint32_t& r0, uint32_t& r1,
                                        uint32_t& r2, uint32_t& r3) {
    asm volatile("ldmatrix.sync.aligned.m8n8.x4.shared.b16 {%0,%1,%2,%3}, [%4];\n"
                 : "=r"(r0), "=r"(r1), "=r"(r2), "=r"(r3) : "r"(addr));
}
__device__ __forceinline__ void mma16816(float* c, const uint32_t* a, const uint32_t* b) {
    asm volatile(
        "mma.sync.aligned.m16n8k16.row.col.f32.f16.f16.f32 "
        "{%0,%1,%2,%3}, {%4,%5,%6,%7}, {%8,%9}, {%0,%1,%2,%3};\n"
        : "+f"(c[0]), "+f"(c[1]), "+f"(c[2]), "+f"(c[3])
        : "r"(a[0]), "r"(a[1]), "r"(a[2]), "r"(a[3]), "r"(b[0]), "r"(b[1]));
}

// ---------------- 1. X fp32 -> fp16 ----------------
__global__ void convert_x_kernel(const float* __restrict__ x, size_t n8) {
    size_t i = (size_t)blockIdx.x * blockDim.x + threadIdx.x;
    if (i >= n8) return;
    const float4* x4 = (const float4*)x;
    float4 a = x4[2 * i];
    float4 b = x4[2 * i + 1];
    union { __half2 h[4]; uint4 u; } r;
    r.h[0] = __floats2half2_rn(a.x, a.y);
    r.h[1] = __floats2half2_rn(a.z, a.w);
    r.h[2] = __floats2half2_rn(b.x, b.y);
    r.h[3] = __floats2half2_rn(b.z, b.w);
    ((uint4*)g_Xh)[i] = r.u;
}

// ---------------- 2a. gate+up transpose+convert (merged, swizzled smem) ----------------
__global__ __launch_bounds__(256) void wconv_gu_kernel(const float* __restrict__ wg,
                                                       const float* __restrict__ wu) {
    __shared__ __half s[64][66];
    const int sel = blockIdx.z >> 4;
    const int e = blockIdx.z & 15;
    const float* src = sel ? wu : wg;
    __half* dst = sel ? g_Wu : g_Wg;
    const int K = HIDDEN, N = INTER;
    int n0 = blockIdx.x * 64, k0 = blockIdx.y * 64;
    const float* sp = src + (size_t)e * K * N + (size_t)k0 * N + n0;
    int tid = threadIdx.x;
    int nc = (tid & 15) * 4;
    #pragma unroll
    for (int p = 0; p < 4; p++) {
        int kr = (tid >> 4) + p * 16;
        int col = nc ^ (p * 16);
        float4 v = *(const float4*)(sp + (size_t)kr * N + nc);
        s[kr][col + 0] = __float2half_rn(v.x);
        s[kr][col + 1] = __float2half_rn(v.y);
        s[kr][col + 2] = __float2half_rn(v.z);
        s[kr][col + 3] = __float2half_rn(v.w);
    }
    __syncthreads();
    __half* dp = dst + (size_t)e * N * K + (size_t)n0 * K + k0;
    int nr = tid >> 2;
    int c = tid & 3;
    int colr = nr ^ (c * 16);
    union { uint2 u2[4]; uint4 u4[2]; } v;
    #pragma unroll
    for (int q = 0; q < 4; q++) {
        int kk = c * 16 + q * 4;
        __half2 lo = __halves2half2(s[kk + 0][colr], s[kk + 1][colr]);
        __half2 hi = __halves2half2(s[kk + 2][colr], s[kk + 3][colr]);
        v.u2[q] = make_uint2(*(uint32_t*)&lo, *(uint32_t*)&hi);
    }
    *(uint4*)(dp + (size_t)nr * K + c * 16) = v.u4[0];
    *(uint4*)(dp + (size_t)nr * K + c * 16 + 8) = v.u4[1];
}

// ---------------- 2b. down-proj transpose+convert (side stream, overlaps gemm1) --------
__global__ __launch_bounds__(128) void wconv_d_kernel(const float* __restrict__ wd) {
    __shared__ __half s[64][66];
    const int e = blockIdx.z;
    const int K = INTER, N = HIDDEN;
    int n0 = blockIdx.x * 64, k0 = blockIdx.y * 64;
    const float* sp = wd + (size_t)e * K * N + (size_t)k0 * N + n0;
    int tid = threadIdx.x;
    int nc = (tid & 15) * 4;
    #pragma unroll
    for (int p = 0; p < 8; p++) {
        int kr = (tid >> 4) + p * 8;
        int col = nc ^ ((p >> 1) * 16);
        float4 v = *(const float4*)(sp + (size_t)kr * N + nc);
        s[kr][col + 0] = __float2half_rn(v.x);
        s[kr][col + 1] = __float2half_rn(v.y);
        s[kr][col + 2] = __float2half_rn(v.z);
        s[kr][col + 3] = __float2half_rn(v.w);
    }
    __syncthreads();
    __half* dp = g_Wd + (size_t)e * N * K + (size_t)n0 * K + k0;
    int nr = tid >> 1;
    #pragma unroll
    for (int it = 0; it < 2; it++) {
        int c = (tid & 1) * 2 + it;
        int colr = nr ^ (c * 16);
        union { uint2 u2[4]; uint4 u4[2]; } v;
        #pragma unroll
        for (int q = 0; q < 4; q++) {
            int kk = c * 16 + q * 4;
            __half2 lo = __halves2half2(s[kk + 0][colr], s[kk + 1][colr]);
            __half2 hi = __halves2half2(s[kk + 2][colr], s[kk + 3][colr]);
            v.u2[q] = make_uint2(*(uint32_t*)&lo, *(uint32_t*)&hi);
        }
        *(uint4*)(dp + (size_t)nr * K + c * 16) = v.u4[0];
        *(uint4*)(dp + (size_t)nr * K + c * 16 + 8) = v.u4[1];
    }
}

// ============================================================================
// GEMM core (R11-proven, non-persistent): 256-thread CTAs, 2/SM, independent
// barrier domains. 8 warps (4m x 2n), warp tile 32m x 64 B-rows.
// mOff = m-tile offset (m-chunked gemm1/gemm2 overlap across streams).
// ============================================================================

// ---------------- 3. fused gate+up GEMM + SwiGLU -> g_H (fp16) ----------------
__global__ __launch_bounds__(256, 2) void gemm1_kernel(int mOff) {
    extern __shared__ __half sm[];
    __half (*sA)[128][PAD] = (__half(*)[128][PAD])sm;
    __half (*sB)[128][PAD] = (__half(*)[128][PAD])(sm + NSTAGE * 128 * PAD);

    const int tid = threadIdx.x;
    const int nB = blockIdx.x * 64;
    const int mTile = blockIdx.y + mOff;
    const int mBase = mTile * BM;
    const int e = mTile >> 4;
    const int NK = HIDDEN / BK;               // 64

    const int lr = tid >> 2, lc = (tid & 3) * 8;
    const __half* gA0 = g_Xh + (size_t)(mBase + lr) * HIDDEN + lc;
    const __half* gA1 = gA0 + (size_t)64 * HIDDEN;
    const __half* gBg = g_Wg + ((size_t)e * INTER + nB + lr) * HIDDEN + lc;
    const __half* gBu = g_Wu + ((size_t)e * INTER + nB + lr) * HIDDEN + lc;

    uint32_t aAd0[NSTAGE], aAd1[NSTAGE], bAd0[NSTAGE], bAd1[NSTAGE];
    #pragma unroll
    for (int s = 0; s < NSTAGE; s++) {
        aAd0[s] = smem_u32(&sA[s][lr][lc]);
        aAd1[s] = smem_u32(&sA[s][lr + 64][lc]);
        bAd0[s] = smem_u32(&sB[s][lr][lc]);
        bAd1[s] = smem_u32(&sB[s][lr + 64][lc]);
    }
    auto load_stage = [&](int s, int k0) {
        cp_async16(aAd0[s], gA0 + k0);
        cp_async16(aAd1[s], gA1 + k0);
        cp_async16(bAd0[s], gBg + k0);
        cp_async16(bAd1[s], gBu + k0);
    };

    float acc[2 * 8 * 4];
    #pragma unroll
    for (int i = 0; i < 64; i++) acc[i] = 0.f;

    const int w = tid >> 5, lane = tid & 31;
    const int wm = (w >> 1) * 32;
    const int wn = (w & 1) * 32;
    const int lrow = lane & 15;
    const int lkb = (lane >> 4) * 8;

    #pragma unroll
    for (int i = 0; i < NSTAGE - 1; i++) { load_stage(i, i * BK); cp_commit(); }

    #pragma unroll 1
    for (int k = 0; k < NK; ++k) {
        cp_wait<NSTAGE - 2>();
        __syncthreads();
        int kn = k + NSTAGE - 1;
        if (kn < NK) load_stage(kn & 3, kn * BK);
        cp_commit();
        const int st = k & 3;
        #pragma unroll
        for (int kk = 0; kk < BK; kk += 16) {
            uint32_t a[2][4];
            uint32_t b[8][2];
            #pragma unroll
            for (int mt = 0; mt < 2; mt++)
                ldsm_x4(smem_u32(&sA[st][wm + mt * 16 + lrow][kk + lkb]),
                        a[mt][0], a[mt][1], a[mt][2], a[mt][3]);
            #pragma unroll
            for (int bt = 0; bt < 2; bt++) {
                uint32_t r0, r1, r2, r3;
                ldsm_x4(smem_u32(&sB[st][wn + bt * 16 + lrow][kk + lkb]), r0, r1, r2, r3);
                b[bt * 2][0] = r0;     b[bt * 2][1] = r2;
                b[bt * 2 + 1][0] = r1; b[bt * 2 + 1][1] = r3;
            }
            #pragma unroll
            for (int bt = 0; bt < 2; bt++) {
                uint32_t r0, r1, r2, r3;
                ldsm_x4(smem_u32(&sB[st][64 + wn + bt * 16 + lrow][kk + lkb]),
                        r0, r1, r2, r3);
                b[4 + bt * 2][0] = r0;     b[4 + bt * 2][1] = r2;
                b[4 + bt * 2 + 1][0] = r1; b[4 + bt * 2 + 1][1] = r3;
            }
            #pragma unroll
            for (int mt = 0; mt < 2; mt++)
                #pragma unroll
                for (int nt = 0; nt < 8; nt++)
                    mma16816(&acc[(mt * 8 + nt) * 4], a[mt], b[nt]);
        }
    }

    // epilogue: nt 0..3 gate, nt+4 up; SwiGLU -> g_H fp16
    const int gr = lane >> 2, gc = (lane & 3) * 2;
    #pragma unroll
    for (int mt = 0; mt < 2; mt++) {
        #pragma unroll
        for (int nt = 0; nt < 4; nt++) {
            const float* g = &acc[(mt * 8 + nt) * 4];
            const float* u = &acc[(mt * 8 + nt + 4) * 4];
            int n = nB + wn + nt * 8 + gc;
            int token = mBase + wm + mt * 16 + gr;
            float h0 = g[0] * u[0] / (1.f + __expf(-g[0]));
            float h1 = g[1] * u[1] / (1.f + __expf(-g[1]));
            float h2 = g[2] * u[2] / (1.f + __expf(-g[2]));
            float h3 = g[3] * u[3] / (1.f + __expf(-g[3]));
            *(__half2*)&g_H[(size_t)token * INTER + n] = __floats2half2_rn(h0, h1);
            *(__half2*)&g_H[(size_t)(token + 8) * INTER + n] = __floats2half2_rn(h2, h3);
        }
    }
}

// ---------------- 4. down GEMM: out = h @ Wd_e (fp32 out), tile 128x128 --------
__global__ __launch_bounds__(256, 2) void gemm2_kernel(float* __restrict__ out, int mOff) {
    extern __shared__ __half sm[];
    __half (*sA)[128][PAD] = (__half(*)[128][PAD])sm;
    __half (*sB)[128][PAD] = (__half(*)[128][PAD])(sm + NSTAGE * 128 * PAD);

    const int tid = threadIdx.x;
    const int nB = blockIdx.x * 128;
    const int mTile = blockIdx.y + mOff;
    const int mBase = mTile * BM;
    const int e = mTile >> 4;
    const int NK = INTER / BK;                // 44

    const int lr = tid >> 2, lc = (tid & 3) * 8;
    const __half* gA0 = g_H + (size_t)(mBase + lr) * INTER + lc;
    const __half* gA1 = gA0 + (size_t)64 * INTER;
    const __half* gB0 = g_Wd + ((size_t)e * HIDDEN + nB + lr) * INTER + lc;
    const __half* gB1 = gB0 + (size_t)64 * INTER;

    uint32_t aAd0[NSTAGE], aAd1[NSTAGE], bAd0[NSTAGE], bAd1[NSTAGE];
    #pragma unroll
    for (int s = 0; s < NSTAGE; s++) {
        aAd0[s] = smem_u32(&sA[s][lr][lc]);
        aAd1[s] = smem_u32(&sA[s][lr + 64][lc]);
        bAd0[s] = smem_u32(&sB[s][lr][lc]);
        bAd1[s] = smem_u32(&sB[s][lr + 64][lc]);
    }
    auto load_stage = [&](int s, int k0) {
        cp_async16(aAd0[s], gA0 + k0);
        cp_async16(aAd1[s], gA1 + k0);
        cp_async16(bAd0[s], gB0 + k0);
        cp_async16(bAd1[s], gB1 + k0);
    };

    float acc[2 * 8 * 4];
    #pragma unroll
    for (int i = 0; i < 64; i++) acc[i] = 0.f;

    const int w = tid >> 5, lane = tid & 31;
    const int wm = (w >> 1) * 32;
    const int wn = (w & 1) * 64;
    const int lrow = lane & 15;
    const int lkb = (lane >> 4) * 8;

    #pragma unroll
    for (int i = 0; i < NSTAGE - 1; i++) { load_stage(i, i * BK); cp_commit(); }

    #pragma unroll 1
    for (int k = 0; k < NK; ++k) {
        cp_wait<NSTAGE - 2>();
        __syncthreads();
        int kn = k + NSTAGE - 1;
        if (kn < NK) load_stage(kn & 3, kn * BK);
        cp_commit();
        const int st = k & 3;
        #pragma unroll
        for (int kk = 0; kk < BK; kk += 16) {
            uint32_t a[2][4];
            uint32_t b[8][2];
            #pragma unroll
            for (int mt = 0; mt < 2; mt++)
                ldsm_x4(smem_u32(&sA[st][wm + mt * 16 + lrow][kk + lkb]),
                        a[mt][0], a[mt][1], a[mt][2], a[mt][3]);
            #pragma unroll
            for (int bt = 0; bt < 4; bt++) {
                uint32_t r0, r1, r2, r3;
                ldsm_x4(smem_u32(&sB[st][wn + bt * 16 + lrow][kk + lkb]), r0, r1, r2, r3);
                b[bt * 2][0] = r0;     b[bt * 2][1] = r2;
                b[bt * 2 + 1][0] = r1; b[bt * 2 + 1][1] = r3;
            }
            #pragma unroll
            for (int mt = 0; mt < 2; mt++)
                #pragma unroll
                for (int nt = 0; nt < 8; nt++)
                    mma16816(&acc[(mt * 8 + nt) * 4], a[mt], b[nt]);
        }
    }

    const int gr = lane >> 2, gc = (lane & 3) * 2;
    #pragma unroll
    for (int mt = 0; mt < 2; mt++) {
        #pragma unroll
        for (int nt = 0; nt < 8; nt++) {
            const float* c = &acc[(mt * 8 + nt) * 4];
            int n = nB + wn + nt * 8 + gc;
            int token = mBase + wm + mt * 16 + gr;
            *(float2*)&out[(size_t)token * HIDDEN + n] = make_float2(c[0], c[1]);
            *(float2*)&out[(size_t)(token + 8) * HIDDEN + n] = make_float2(c[2], c[3]);
        }
    }
}

// ---------------- launch ----------------
extern "C" void kernel_launch(void* const* d_in, const int* in_sizes, int n_in,
                              void* d_out, int out_size) {
    const float* x  = (const float*)d_in[0];
    const float* wg = (const float*)d_in[1];
    const float* wu = (const float*)d_in[2];
    const float* wd = (const float*)d_in[3];
    (void)in_sizes; (void)n_in; (void)out_size;

    static cudaStream_t s1 = nullptr, s2 = nullptr;
    static cudaEvent_t evFork = nullptr, evWd = nullptr, evB = nullptr;
    if (!s1) {
        cudaStreamCreateWithFlags(&s1, cudaStreamNonBlocking);
        cudaStreamCreateWithFlags(&s2, cudaStreamNonBlocking);
        cudaEventCreateWithFlags(&evFork, cudaEventDisableTiming);
        cudaEventCreateWithFlags(&evWd, cudaEventDisableTiming);
        cudaEventCreateWithFlags(&evB, cudaEventDisableTiming);
        cudaFuncSetAttribute(gemm1_kernel, cudaFuncAttributeMaxDynamicSharedMemorySize,
                             SMEM_BYTES);
        cudaFuncSetAttribute(gemm2_kernel, cudaFuncAttributeMaxDynamicSharedMemorySize,
                             SMEM_BYTES);
    }

    const int MT = TOKENS / BM;       // 256 m-tiles
    const int MTH = MT / 2;           // 128 per half

    // converts first (full DRAM BW)
    size_t n8 = (size_t)TOKENS * HIDDEN / 8;
    convert_x_kernel<<<(unsigned)((n8 + 255) / 256), 256>>>(x, n8);
    wconv_gu_kernel<<<dim3(INTER / 64, HIDDEN / 64, 2 * NEXP), 256>>>(wg, wu);
    cudaEventRecord(evFork, 0);

    // s1: wconv_d overlaps gemm1 (compute-bound, spare DRAM BW)
    cudaStreamWaitEvent(s1, evFork, 0);
    wconv_d_kernel<<<dim3(HIDDEN / 64, INTER / 64, NEXP), 128, 0, s1>>>(wd);
    cudaEventRecord(evWd, s1);

    // m-chunked pipelines: half A on default stream, half B on s2.
    // gemm2_A backfills gemm1_B's tail (independent SM pools, event-ordered deps).
    cudaStreamWaitEvent(s2, evFork, 0);
    gemm1_kernel<<<dim3(INTER / 64, MTH), 256, SMEM_BYTES>>>(0);                 // A
    gemm1_kernel<<<dim3(INTER / 64, MTH), 256, SMEM_BYTES, s2>>>(MTH);           // B

    cudaStreamWaitEvent(0, evWd, 0);
    gemm2_kernel<<<dim3(HIDDEN / 128, MTH), 256, SMEM_BYTES>>>((float*)d_out, 0);   // A
    cudaStreamWaitEvent(s2, evWd, 0);
    gemm2_kernel<<<dim3(HIDDEN / 128, MTH), 256, SMEM_BYTES, s2>>>((float*)d_out, MTH); // B
    cudaEventRecord(evB, s2);

    // join everything back to the capture stream
    cudaStreamWaitEvent(0, evB, 0);
}

// round 16
// speedup vs baseline: 1.0909x; 1.0115x over previous
#include <cuda_runtime.h>
#include <cuda_fp16.h>
#include <cstdint>
#include <cstddef>

#define TOKENS 32768
#define HIDDEN 2048
#define INTER  1408
#define NEXP   16
#define TPE    2048

#define BM 128
#define BK 32
#define PAD 40
#define NSTAGE 4
#define SMEM_BYTES (NSTAGE * (128 * PAD + 128 * PAD) * 2)

// ---------------- static device scratch ----------------
__device__ __align__(128) __half g_Xh[(size_t)TOKENS * HIDDEN];
__device__ __align__(128) __half g_Wg[(size_t)NEXP * INTER * HIDDEN];   // [e][n][k]
__device__ __align__(128) __half g_Wu[(size_t)NEXP * INTER * HIDDEN];   // [e][n][k]
__device__ __align__(128) __half g_Wd[(size_t)NEXP * HIDDEN * INTER];   // [e][n][k]
__device__ __align__(128) __half g_H [(size_t)TOKENS * INTER];

// ---------------- helpers ----------------
__device__ __forceinline__ uint32_t smem_u32(const void* p) {
    return (uint32_t)__cvta_generic_to_shared(p);
}
__device__ __forceinline__ void cp_async16(uint32_t dst, const void* src) {
    asm volatile("cp.async.cg.shared.global [%0], [%1], 16;\n" :: "r"(dst), "l"(src));
}
__device__ __forceinline__ void cp_commit() {
    asm volatile("cp.async.commit_group;\n" ::: "memory");
}
template <int N>
__device__ __forceinline__ void cp_wait() {
    asm volatile("cp.async.wait_group %0;\n" :: "n"(N) : "memory");
}
__device__ __forceinline__ void ldsm_x4(uint32_t addr, uint32_t& r0, uint32_t& r1,
                                        uint32_t& r2, uint32_t& r3) {
    asm volatile("ldmatrix.sync.aligned.m8n8.x4.shared.b16 {%0,%1,%2,%3}, [%4];\n"
                 : "=r"(r0), "=r"(r1), "=r"(r2), "=r"(r3) : "r"(addr));
}
__device__ __forceinline__ void mma16816(float* c, const uint32_t* a, const uint32_t* b) {
    asm volatile(
        "mma.sync.aligned.m16n8k16.row.col.f32.f16.f16.f32 "
        "{%0,%1,%2,%3}, {%4,%5,%6,%7}, {%8,%9}, {%0,%1,%2,%3};\n"
        : "+f"(c[0]), "+f"(c[1]), "+f"(c[2]), "+f"(c[3])
        : "r"(a[0]), "r"(a[1]), "r"(a[2]), "r"(a[3]), "r"(b[0]), "r"(b[1]));
}

// ---------------- 1. X fp32 -> fp16 (token-chunked) ----------------
__global__ void convert_x_kernel(const float* __restrict__ x, size_t off8, size_t n8) {
    size_t i = off8 + (size_t)blockIdx.x * blockDim.x + threadIdx.x;
    if (i >= off8 + n8) return;
    const float4* x4 = (const float4*)x;
    float4 a = x4[2 * i];
    float4 b = x4[2 * i + 1];
    union { __half2 h[4]; uint4 u; } r;
    r.h[0] = __floats2half2_rn(a.x, a.y);
    r.h[1] = __floats2half2_rn(a.z, a.w);
    r.h[2] = __floats2half2_rn(b.x, b.y);
    r.h[3] = __floats2half2_rn(b.z, b.w);
    ((uint4*)g_Xh)[i] = r.u;
}

// ---------------- 2a. gate+up transpose+convert (expert-chunked) ----------------
__global__ __launch_bounds__(256) void wconv_gu_kernel(const float* __restrict__ wg,
                                                       const float* __restrict__ wu,
                                                       int eOff) {
    __shared__ __half s[64][66];
    const int sel = blockIdx.z >> 3;           // 0=gate, 1=up (8 experts per chunk)
    const int e = (blockIdx.z & 7) + eOff;
    const float* src = sel ? wu : wg;
    __half* dst = sel ? g_Wu : g_Wg;
    const int K = HIDDEN, N = INTER;
    int n0 = blockIdx.x * 64, k0 = blockIdx.y * 64;
    const float* sp = src + (size_t)e * K * N + (size_t)k0 * N + n0;
    int tid = threadIdx.x;
    int nc = (tid & 15) * 4;
    #pragma unroll
    for (int p = 0; p < 4; p++) {
        int kr = (tid >> 4) + p * 16;
        int col = nc ^ (p * 16);
        float4 v = *(const float4*)(sp + (size_t)kr * N + nc);
        s[kr][col + 0] = __float2half_rn(v.x);
        s[kr][col + 1] = __float2half_rn(v.y);
        s[kr][col + 2] = __float2half_rn(v.z);
        s[kr][col + 3] = __float2half_rn(v.w);
    }
    __syncthreads();
    __half* dp = dst + (size_t)e * N * K + (size_t)n0 * K + k0;
    int nr = tid >> 2;
    int c = tid & 3;
    int colr = nr ^ (c * 16);
    union { uint2 u2[4]; uint4 u4[2]; } v;
    #pragma unroll
    for (int q = 0; q < 4; q++) {
        int kk = c * 16 + q * 4;
        __half2 lo = __halves2half2(s[kk + 0][colr], s[kk + 1][colr]);
        __half2 hi = __halves2half2(s[kk + 2][colr], s[kk + 3][colr]);
        v.u2[q] = make_uint2(*(uint32_t*)&lo, *(uint32_t*)&hi);
    }
    *(uint4*)(dp + (size_t)nr * K + c * 16) = v.u4[0];
    *(uint4*)(dp + (size_t)nr * K + c * 16 + 8) = v.u4[1];
}

// ---------------- 2b. down-proj transpose+convert (side stream, overlaps gemm1) --------
__global__ __launch_bounds__(128) void wconv_d_kernel(const float* __restrict__ wd) {
    __shared__ __half s[64][66];
    const int e = blockIdx.z;
    const int K = INTER, N = HIDDEN;
    int n0 = blockIdx.x * 64, k0 = blockIdx.y * 64;
    const float* sp = wd + (size_t)e * K * N + (size_t)k0 * N + n0;
    int tid = threadIdx.x;
    int nc = (tid & 15) * 4;
    #pragma unroll
    for (int p = 0; p < 8; p++) {
        int kr = (tid >> 4) + p * 8;
        int col = nc ^ ((p >> 1) * 16);
        float4 v = *(const float4*)(sp + (size_t)kr * N + nc);
        s[kr][col + 0] = __float2half_rn(v.x);
        s[kr][col + 1] = __float2half_rn(v.y);
        s[kr][col + 2] = __float2half_rn(v.z);
        s[kr][col + 3] = __float2half_rn(v.w);
    }
    __syncthreads();
    __half* dp = g_Wd + (size_t)e * N * K + (size_t)n0 * K + k0;
    int nr = tid >> 1;
    #pragma unroll
    for (int it = 0; it < 2; it++) {
        int c = (tid & 1) * 2 + it;
        int colr = nr ^ (c * 16);
        union { uint2 u2[4]; uint4 u4[2]; } v;
        #pragma unroll
        for (int q = 0; q < 4; q++) {
            int kk = c * 16 + q * 4;
            __half2 lo = __halves2half2(s[kk + 0][colr], s[kk + 1][colr]);
            __half2 hi = __halves2half2(s[kk + 2][colr], s[kk + 3][colr]);
            v.u2[q] = make_uint2(*(uint32_t*)&lo, *(uint32_t*)&hi);
        }
        *(uint4*)(dp + (size_t)nr * K + c * 16) = v.u4[0];
        *(uint4*)(dp + (size_t)nr * K + c * 16 + 8) = v.u4[1];
    }
}

// ============================================================================
// GEMM core (R11/R15-proven): 256-thread CTAs, 2/SM, independent barrier
// domains. 8 warps (4m x 2n), warp tile 32m x 64 B-rows. mOff = m-tile offset.
// ============================================================================

// ---------------- 3. fused gate+up GEMM + SwiGLU -> g_H (fp16) ----------------
__global__ __launch_bounds__(256, 2) void gemm1_kernel(int mOff) {
    extern __shared__ __half sm[];
    __half (*sA)[128][PAD] = (__half(*)[128][PAD])sm;
    __half (*sB)[128][PAD] = (__half(*)[128][PAD])(sm + NSTAGE * 128 * PAD);

    const int tid = threadIdx.x;
    const int nB = blockIdx.x * 64;
    const int mTile = blockIdx.y + mOff;
    const int mBase = mTile * BM;
    const int e = mTile >> 4;
    const int NK = HIDDEN / BK;               // 64

    const int lr = tid >> 2, lc = (tid & 3) * 8;
    const __half* gA0 = g_Xh + (size_t)(mBase + lr) * HIDDEN + lc;
    const __half* gA1 = gA0 + (size_t)64 * HIDDEN;
    const __half* gBg = g_Wg + ((size_t)e * INTER + nB + lr) * HIDDEN + lc;
    const __half* gBu = g_Wu + ((size_t)e * INTER + nB + lr) * HIDDEN + lc;

    uint32_t aAd0[NSTAGE], aAd1[NSTAGE], bAd0[NSTAGE], bAd1[NSTAGE];
    #pragma unroll
    for (int s = 0; s < NSTAGE; s++) {
        aAd0[s] = smem_u32(&sA[s][lr][lc]);
        aAd1[s] = smem_u32(&sA[s][lr + 64][lc]);
        bAd0[s] = smem_u32(&sB[s][lr][lc]);
        bAd1[s] = smem_u32(&sB[s][lr + 64][lc]);
    }
    auto load_stage = [&](int s, int k0) {
        cp_async16(aAd0[s], gA0 + k0);
        cp_async16(aAd1[s], gA1 + k0);
        cp_async16(bAd0[s], gBg + k0);
        cp_async16(bAd1[s], gBu + k0);
    };

    float acc[2 * 8 * 4];
    #pragma unroll
    for (int i = 0; i < 64; i++) acc[i] = 0.f;

    const int w = tid >> 5, lane = tid & 31;
    const int wm = (w >> 1) * 32;
    const int wn = (w & 1) * 32;
    const int lrow = lane & 15;
    const int lkb = (lane >> 4) * 8;

    #pragma unroll
    for (int i = 0; i < NSTAGE - 1; i++) { load_stage(i, i * BK); cp_commit(); }

    #pragma unroll 1
    for (int k = 0; k < NK; ++k) {
        cp_wait<NSTAGE - 2>();
        __syncthreads();
        int kn = k + NSTAGE - 1;
        if (kn < NK) load_stage(kn & 3, kn * BK);
        cp_commit();
        const int st = k & 3;
        #pragma unroll
        for (int kk = 0; kk < BK; kk += 16) {
            uint32_t a[2][4];
            uint32_t b[8][2];
            #pragma unroll
            for (int mt = 0; mt < 2; mt++)
                ldsm_x4(smem_u32(&sA[st][wm + mt * 16 + lrow][kk + lkb]),
                        a[mt][0], a[mt][1], a[mt][2], a[mt][3]);
            #pragma unroll
            for (int bt = 0; bt < 2; bt++) {
                uint32_t r0, r1, r2, r3;
                ldsm_x4(smem_u32(&sB[st][wn + bt * 16 + lrow][kk + lkb]), r0, r1, r2, r3);
                b[bt * 2][0] = r0;     b[bt * 2][1] = r2;
                b[bt * 2 + 1][0] = r1; b[bt * 2 + 1][1] = r3;
            }
            #pragma unroll
            for (int bt = 0; bt < 2; bt++) {
                uint32_t r0, r1, r2, r3;
                ldsm_x4(smem_u32(&sB[st][64 + wn + bt * 16 + lrow][kk + lkb]),
                        r0, r1, r2, r3);
                b[4 + bt * 2][0] = r0;     b[4 + bt * 2][1] = r2;
                b[4 + bt * 2 + 1][0] = r1; b[4 + bt * 2 + 1][1] = r3;
            }
            #pragma unroll
            for (int mt = 0; mt < 2; mt++)
                #pragma unroll
                for (int nt = 0; nt < 8; nt++)
                    mma16816(&acc[(mt * 8 + nt) * 4], a[mt], b[nt]);
        }
    }

    // epilogue: nt 0..3 gate, nt+4 up; SwiGLU -> g_H fp16
    const int gr = lane >> 2, gc = (lane & 3) * 2;
    #pragma unroll
    for (int mt = 0; mt < 2; mt++) {
        #pragma unroll
        for (int nt = 0; nt < 4; nt++) {
            const float* g = &acc[(mt * 8 + nt) * 4];
            const float* u = &acc[(mt * 8 + nt + 4) * 4];
            int n = nB + wn + nt * 8 + gc;
            int token = mBase + wm + mt * 16 + gr;
            float h0 = g[0] * u[0] / (1.f + __expf(-g[0]));
            float h1 = g[1] * u[1] / (1.f + __expf(-g[1]));
            float h2 = g[2] * u[2] / (1.f + __expf(-g[2]));
            float h3 = g[3] * u[3] / (1.f + __expf(-g[3]));
            *(__half2*)&g_H[(size_t)token * INTER + n] = __floats2half2_rn(h0, h1);
            *(__half2*)&g_H[(size_t)(token + 8) * INTER + n] = __floats2half2_rn(h2, h3);
        }
    }
}

// ---------------- 4. down GEMM: out = h @ Wd_e (fp32 out), tile 128x128 --------
__global__ __launch_bounds__(256, 2) void gemm2_kernel(float* __restrict__ out, int mOff) {
    extern __shared__ __half sm[];
    __half (*sA)[128][PAD] = (__half(*)[128][PAD])sm;
    __half (*sB)[128][PAD] = (__half(*)[128][PAD])(sm + NSTAGE * 128 * PAD);

    const int tid = threadIdx.x;
    const int nB = blockIdx.x * 128;
    const int mTile = blockIdx.y + mOff;
    const int mBase = mTile * BM;
    const int e = mTile >> 4;
    const int NK = INTER / BK;                // 44

    const int lr = tid >> 2, lc = (tid & 3) * 8;
    const __half* gA0 = g_H + (size_t)(mBase + lr) * INTER + lc;
    const __half* gA1 = gA0 + (size_t)64 * INTER;
    const __half* gB0 = g_Wd + ((size_t)e * HIDDEN + nB + lr) * INTER + lc;
    const __half* gB1 = gB0 + (size_t)64 * INTER;

    uint32_t aAd0[NSTAGE], aAd1[NSTAGE], bAd0[NSTAGE], bAd1[NSTAGE];
    #pragma unroll
    for (int s = 0; s < NSTAGE; s++) {
        aAd0[s] = smem_u32(&sA[s][lr][lc]);
        aAd1[s] = smem_u32(&sA[s][lr + 64][lc]);
        bAd0[s] = smem_u32(&sB[s][lr][lc]);
        bAd1[s] = smem_u32(&sB[s][lr + 64][lc]);
    }
    auto load_stage = [&](int s, int k0) {
        cp_async16(aAd0[s], gA0 + k0);
        cp_async16(aAd1[s], gA1 + k0);
        cp_async16(bAd0[s], gB0 + k0);
        cp_async16(bAd1[s], gB1 + k0);
    };

    float acc[2 * 8 * 4];
    #pragma unroll
    for (int i = 0; i < 64; i++) acc[i] = 0.f;

    const int w = tid >> 5, lane = tid & 31;
    const int wm = (w >> 1) * 32;
    const int wn = (w & 1) * 64;
    const int lrow = lane & 15;
    const int lkb = (lane >> 4) * 8;

    #pragma unroll
    for (int i = 0; i < NSTAGE - 1; i++) { load_stage(i, i * BK); cp_commit(); }

    #pragma unroll 1
    for (int k = 0; k < NK; ++k) {
        cp_wait<NSTAGE - 2>();
        __syncthreads();
        int kn = k + NSTAGE - 1;
        if (kn < NK) load_stage(kn & 3, kn * BK);
        cp_commit();
        const int st = k & 3;
        #pragma unroll
        for (int kk = 0; kk < BK; kk += 16) {
            uint32_t a[2][4];
            uint32_t b[8][2];
            #pragma unroll
            for (int mt = 0; mt < 2; mt++)
                ldsm_x4(smem_u32(&sA[st][wm + mt * 16 + lrow][kk + lkb]),
                        a[mt][0], a[mt][1], a[mt][2], a[mt][3]);
            #pragma unroll
            for (int bt = 0; bt < 4; bt++) {
                uint32_t r0, r1, r2, r3;
                ldsm_x4(smem_u32(&sB[st][wn + bt * 16 + lrow][kk + lkb]), r0, r1, r2, r3);
                b[bt * 2][0] = r0;     b[bt * 2][1] = r2;
                b[bt * 2 + 1][0] = r1; b[bt * 2 + 1][1] = r3;
            }
            #pragma unroll
            for (int mt = 0; mt < 2; mt++)
                #pragma unroll
                for (int nt = 0; nt < 8; nt++)
                    mma16816(&acc[(mt * 8 + nt) * 4], a[mt], b[nt]);
        }
    }

    const int gr = lane >> 2, gc = (lane & 3) * 2;
    #pragma unroll
    for (int mt = 0; mt < 2; mt++) {
        #pragma unroll
        for (int nt = 0; nt < 8; nt++) {
            const float* c = &acc[(mt * 8 + nt) * 4];
            int n = nB + wn + nt * 8 + gc;
            int token = mBase + wm + mt * 16 + gr;
            *(float2*)&out[(size_t)token * HIDDEN + n] = make_float2(c[0], c[1]);
            *(float2*)&out[(size_t)(token + 8) * HIDDEN + n] = make_float2(c[2], c[3]);
        }
    }
}

// ---------------- launch ----------------
extern "C" void kernel_launch(void* const* d_in, const int* in_sizes, int n_in,
                              void* d_out, int out_size) {
    const float* x  = (const float*)d_in[0];
    const float* wg = (const float*)d_in[1];
    const float* wu = (const float*)d_in[2];
    const float* wd = (const float*)d_in[3];
    (void)in_sizes; (void)n_in; (void)out_size;

    static cudaStream_t s1 = nullptr, s2 = nullptr;
    static cudaEvent_t evA = nullptr, evBc = nullptr, evWd = nullptr, evB = nullptr;
    if (!s1) {
        cudaStreamCreateWithFlags(&s1, cudaStreamNonBlocking);
        cudaStreamCreateWithFlags(&s2, cudaStreamNonBlocking);
        cudaEventCreateWithFlags(&evA, cudaEventDisableTiming);
        cudaEventCreateWithFlags(&evBc, cudaEventDisableTiming);
        cudaEventCreateWithFlags(&evWd, cudaEventDisableTiming);
        cudaEventCreateWithFlags(&evB, cudaEventDisableTiming);
        cudaFuncSetAttribute(gemm1_kernel, cudaFuncAttributeMaxDynamicSharedMemorySize,
                             SMEM_BYTES);
        cudaFuncSetAttribute(gemm2_kernel, cudaFuncAttributeMaxDynamicSharedMemorySize,
                             SMEM_BYTES);
    }

    const int MT = TOKENS / BM;       // 256 m-tiles
    const int MTH = MT / 2;           // 128 per half (experts 0-7 / 8-15)
    const size_t n8h = (size_t)(TOKENS / 2) * HIDDEN / 8;

    // --- chunk A converts (full DRAM BW, serial) -> gemm1_A starts early ---
    convert_x_kernel<<<(unsigned)((n8h + 255) / 256), 256>>>(x, 0, n8h);
    wconv_gu_kernel<<<dim3(INTER / 64, HIDDEN / 64, 16), 256>>>(wg, wu, 0);
    cudaEventRecord(evA, 0);

    gemm1_kernel<<<dim3(INTER / 64, MTH), 256, SMEM_BYTES>>>(0);             // A

    // --- chunk B converts on s2, overlapping gemm1_A (spare DRAM BW) ---
    cudaStreamWaitEvent(s2, evA, 0);
    convert_x_kernel<<<(unsigned)((n8h + 255) / 256), 256, 0, s2>>>(x, n8h, n8h);
    wconv_gu_kernel<<<dim3(INTER / 64, HIDDEN / 64, 16), 256, 0, s2>>>(wg, wu, 8);
    cudaEventRecord(evBc, s2);
    gemm1_kernel<<<dim3(INTER / 64, MTH), 256, SMEM_BYTES, s2>>>(MTH);       // B

    // --- wconv_d on s1 after B converts, overlapping gemm1 ---
    cudaStreamWaitEvent(s1, evBc, 0);
    wconv_d_kernel<<<dim3(HIDDEN / 64, INTER / 64, NEXP), 128, 0, s1>>>(wd);
    cudaEventRecord(evWd, s1);

    // --- gemm2 halves (A backfills gemm1_B's tail) ---
    cudaStreamWaitEvent(0, evWd, 0);
    gemm2_kernel<<<dim3(HIDDEN / 128, MTH), 256, SMEM_BYTES>>>((float*)d_out, 0);
    cudaStreamWaitEvent(s2, evWd, 0);
    gemm2_kernel<<<dim3(HIDDEN / 128, MTH), 256, SMEM_BYTES, s2>>>((float*)d_out, MTH);
    cudaEventRecord(evB, s2);

    cudaStreamWaitEvent(0, evB, 0);
}